// round 14
// baseline (speedup 1.0000x reference)
#include <cuda_runtime.h>

#define Bb 8
#define Nn 64
#define Kk 64
#define Tt 128
#define NB1 65
#define KK2 4096
#define SSTR 68
#define SMEM_BYTES (2 * 128 * SSTR * 4)   // 69632 -> 3 CTAs/SM
#define CSTR 32
#define NF 64

typedef unsigned long long ull;

__device__ __align__(256) float g_chart[NB1 * NB1 * Bb * Kk];
__device__ __align__(256) float g_pairs[2][512 * KK2];
__device__ __align__(256) float g_part[2][8][32][64 * 64];
__device__ __align__(256) float g_U1[512 * 4096];
__device__ __align__(256) float g_V2[512 * 4096];
__device__ __align__(256) float g_rT[64 * 4096];
__device__ __align__(256) float g_rT2[64 * 4096];

__device__ int g_lvl;
__device__ int g_lvlcnt[NB1 * CSTR];
__device__ int g_fdone[NF * CSTR];
__device__ int g_pre_ready[NB1 * 8 * CSTR];
__device__ int g_chunkdone[NB1 * 8 * CSTR];
__device__ int g_c0[8 * CSTR];
__device__ int g_c0m;
__device__ int g_rt;
__device__ int g_uv;
__device__ unsigned g_arrive = 0;
__device__ unsigned g_release = 0;

__device__ __forceinline__ int cidx(int i, int j, int b, int k) {
    return ((i * NB1 + j) * Bb + b) * Kk + k;
}
__device__ __forceinline__ ull pack2(float lo, float hi) {
    ull r; asm("mov.b64 %0, {%1, %2};" : "=l"(r) : "f"(lo), "f"(hi)); return r;
}
__device__ __forceinline__ void fma2(ull& d, ull a, ull b) {
    asm("fma.rn.f32x2 %0, %1, %2, %0;" : "+l"(d) : "l"(a), "l"(b));
}
__device__ __forceinline__ float2 unpk(ull v) {
    float2 o; asm("mov.b64 {%0, %1}, %2;" : "=f"(o.x), "=f"(o.y) : "l"(v)); return o;
}
__device__ __forceinline__ int ld_acq(const int* p) {
    int v; asm volatile("ld.acquire.gpu.global.b32 %0, [%1];" : "=r"(v) : "l"(p) : "memory"); return v;
}
__device__ __forceinline__ void red_rel(int* p, int v) {
    asm volatile("red.release.gpu.global.add.s32 [%0], %1;" :: "l"(p), "r"(v) : "memory");
}
__device__ __forceinline__ int atom_ar(int* p, int v) {
    int o; asm volatile("atom.acq_rel.gpu.global.add.s32 %0, [%1], %2;" : "=r"(o) : "l"(p), "r"(v) : "memory"); return o;
}
__device__ __forceinline__ void st_rel(int* p, int v) {
    asm volatile("st.release.gpu.global.b32 [%0], %1;" :: "l"(p), "r"(v) : "memory");
}
__device__ __forceinline__ void spin_ctr(int* p, int target) {
    if (threadIdx.x == 0) { while (ld_acq(p) < target) { } }
    __syncthreads();
}
__device__ __forceinline__ void spin_lvl(int target) {
    if (threadIdx.x == 0) { while (ld_acq(&g_lvl) < target) { } }
    __syncthreads();
}
__device__ __forceinline__ void gbar(unsigned target, int nblk) {
    __threadfence();
    __syncthreads();
    if (threadIdx.x == 0) {
        unsigned old = atomicAdd(&g_arrive, 1u);
        if (old == (unsigned)(nblk - 1)) {
            g_arrive = 0;
            __threadfence();
            *(volatile unsigned*)&g_release = target;
        } else {
            while ((int)(*(volatile unsigned*)&g_release - target) < 0) __nanosleep(64);
            __threadfence();
        }
    }
    __syncthreads();
}

// pair rank-1 accumulation for level s3 (splits 2..s3-2), rows distributed over [who, np)
// chart is write-once and reads are acquire-gated -> L1-cached __ldg is safe and
// cuts L2 traffic ~4x (R was 8x-redundant across warps under __ldcg).
__device__ __forceinline__ void pair_level(int s3, int who, int np, int tid) {
    const int rows3 = (65 - s3) * Bb;
    float* const pairn = g_pairs[s3 & 1];
    const int tx = tid & 15, ty = tid >> 4;
    const int x0 = ty * 4, y0r = tx * 4;
    for (int u = who; u < rows3; u += np) {
        const int cell = u >> 3, b = u & 7;
        ull acc[4][2];
        #pragma unroll
        for (int i = 0; i < 4; i++) { acc[i][0] = 0ull; acc[i][1] = 0ull; }
        const float* Lbase = &g_chart[cidx(cell, cell, b, x0)];
        const float* Rbase = &g_chart[cidx(cell, cell + s3, b, y0r)];
        #pragma unroll 4
        for (int sp = 2; sp <= s3 - 2; sp++) {
            float4 L = __ldg((const float4*)(Lbase + (size_t)sp * (Bb * Kk)));
            float4 R = __ldg((const float4*)(Rbase + (size_t)sp * (NB1 * Bb * Kk)));
            ull r01 = pack2(R.x, R.y), r23 = pack2(R.z, R.w);
            ull l;
            l = pack2(L.x, L.x); fma2(acc[0][0], l, r01); fma2(acc[0][1], l, r23);
            l = pack2(L.y, L.y); fma2(acc[1][0], l, r01); fma2(acc[1][1], l, r23);
            l = pack2(L.z, L.z); fma2(acc[2][0], l, r01); fma2(acc[2][1], l, r23);
            l = pack2(L.w, L.w); fma2(acc[3][0], l, r01); fma2(acc[3][1], l, r23);
        }
        #pragma unroll
        for (int i = 0; i < 4; i++) {
            float2 e0 = unpk(acc[i][0]), e1 = unpk(acc[i][1]);
            float4 o; o.x = e0.x; o.y = e0.y; o.z = e1.x; o.w = e1.y;
            *(float4*)&pairn[(size_t)u * KK2 + (x0 + i) * Kk + y0r] = o;
        }
        __syncthreads();
        if (tid == 0) red_rel(&g_pre_ready[(s3 * 8 + (u >> 6)) * CSTR], 1);
    }
}

__global__ void __launch_bounds__(256, 3)
rbn_persistent(const float* __restrict__ seq, const float* __restrict__ rule,
               const float* __restrict__ emit, const float* __restrict__ prior,
               float* __restrict__ out, int nblk)
{
    extern __shared__ float smem[];
    const int tid = threadIdx.x;
    const int bid = blockIdx.x;
    const int w = tid >> 5, lane = tid & 31;
    const unsigned gen = *(volatile unsigned*)&g_release;

    // ===== Phase 0: span-1 cells =====
    for (int u = bid; u < Nn * Bb; u += nblk) {
        int i = u >> 3, b = u & 7;
        const float* srow = seq + (b * Nn + i) * Tt;
        #pragma unroll
        for (int aa = 0; aa < 8; aa++) {
            int a = w * 8 + aa;
            float p = 0.f;
            #pragma unroll
            for (int q = 0; q < 4; q++) {
                int t2 = lane + q * 32;
                p += emit[a * Tt + t2] * srow[t2];
            }
            #pragma unroll
            for (int off = 16; off; off >>= 1) p += __shfl_down_sync(0xffffffffu, p, off);
            if (lane == 0) g_chart[cidx(i, i + 1, b, a)] = p;
        }
        __syncthreads();
        if (tid == 0) {
            int old = atom_ar(&g_c0[(u & 7) * CSTR], 1);
            if (old == (Nn * Bb / 8) - 1) {
                int mo = atom_ar(&g_c0m, 1);
                if (mo == 7) st_rel(&g_lvl, 1);
            }
        }
    }

    if (bid < 63) {
        // ===== FRONT CTA f: systolic wavefront + fused partial-reduction =====
        const int f = bid;
        float* sR    = smem;
        float* sPrev = smem + 512;
        float* sAcc  = smem + 1024;
        float* sVp   = smem + 1536;

        spin_ctr(&g_uv, 256);

        const int slot = tid & 127, half = tid >> 7;
        const int b = slot >> 4, quad = slot & 15;
        const float* U1row = &g_U1[((size_t)(f * 8 + b)) << 12];
        const int y0 = half * 32;
        const int tile = f >> 3;

        for (int s = 2; s <= Nn - f; s++) {
            if (s >= 3) spin_ctr(&g_fdone[(f + 1) * CSTR], s - 1);
            if (s >= 4) spin_ctr(&g_chunkdone[(s * 8 + tile) * CSTR], 32);

            if (tid < 128) {
                int bb = tid >> 4, qq = tid & 15;
                *(float4*)&sR[bb * 64 + qq * 4] =
                    __ldg((const float4*)&g_chart[cidx(f + 1, f + s, bb, qq * 4)]);
            } else if (s >= 4) {
                int t2 = tid - 128; int bb = t2 >> 4, qq = t2 & 15;
                const float* pp = &g_part[s & 1][tile][0][((((f & 7) * 8 + bb)) << 6) + qq * 4];
                float4 a4 = make_float4(0.f, 0.f, 0.f, 0.f);
                #pragma unroll
                for (int cc = 0; cc < 32; cc++) {
                    float4 v = __ldcg((const float4*)(pp + (size_t)cc * 4096));
                    a4.x += v.x; a4.y += v.y; a4.z += v.z; a4.w += v.w;
                }
                *(float4*)&sVp[bb * 64 + qq * 4] = a4;
            }
            __syncthreads();

            float4 acc = make_float4(0.f, 0.f, 0.f, 0.f);
            if (s >= 3) {
                const float* V2row = &g_V2[((size_t)((f + s - 1) * 8 + b)) << 12];
                #pragma unroll 8
                for (int y = y0; y < y0 + 32; y++) {
                    float r = sR[b * 64 + y];
                    float4 u = __ldg((const float4*)&U1row[y * 64 + quad * 4]);
                    acc.x += u.x * r; acc.y += u.y * r; acc.z += u.z * r; acc.w += u.w * r;
                    float l = sPrev[b * 64 + y];
                    float4 v = __ldg((const float4*)&V2row[y * 64 + quad * 4]);
                    acc.x += v.x * l; acc.y += v.y * l; acc.z += v.z * l; acc.w += v.w * l;
                }
            } else {
                #pragma unroll 8
                for (int y = y0; y < y0 + 32; y++) {
                    float r = sR[b * 64 + y];
                    float4 u = __ldg((const float4*)&U1row[y * 64 + quad * 4]);
                    acc.x += u.x * r; acc.y += u.y * r; acc.z += u.z * r; acc.w += u.w * r;
                }
            }
            if (half) *(float4*)&sAcc[slot * 4] = acc;
            __syncthreads();
            if (!half) {
                float4 o = acc;
                float4 h = *(const float4*)&sAcc[slot * 4];
                o.x += h.x; o.y += h.y; o.z += h.z; o.w += h.w;
                if (s >= 4) {
                    float4 vp = *(const float4*)&sVp[b * 64 + quad * 4];
                    o.x += vp.x; o.y += vp.y; o.z += vp.z; o.w += vp.w;
                }
                *(float4*)&g_chart[cidx(f, f + s, b, quad * 4)] = o;
                *(float4*)&sPrev[b * 64 + quad * 4] = o;
            }
            __syncthreads();
            if (tid == 0) {
                st_rel(&g_fdone[f * CSTR], s);
                red_rel(&g_lvlcnt[s * CSTR], 1);
            }
        }

        if (f == 0) {
            __syncthreads();
            const int bb = w;
            float p = prior[lane] * sPrev[bb * 64 + lane]
                    + prior[lane + 32] * sPrev[bb * 64 + lane + 32];
            #pragma unroll
            for (int off = 16; off; off >>= 1) p += __shfl_down_sync(0xffffffffu, p, off);
            if (lane == 0) out[bb] = p;
        }
    } else if (bid == 63) {
        // ===== PUBLISHER =====
        for (int s = 2; s <= Nn; s++) {
            spin_ctr(&g_lvlcnt[s * CSTR], 65 - s);
            if (tid == 0) st_rel(&g_lvl, s);
        }
    } else {
        // ===== BACKGROUND =====
        const int j = bid - NF;
        const int nbg = nblk - NF;
        const int tx = tid & 15, ty = tid >> 4;
        const int x0 = ty * 4, y0r = tx * 4;
        float* sA = smem;
        float* sB = smem + 128 * SSTR;

        // rule transposes
        for (int u = j; u < 64; u += nbg) {
            for (int idx = tid; idx < 4096; idx += 256) {
                int c1 = idx >> 6, a = idx & 63;
                g_rT [(size_t)u * 4096 + c1 * 64 + a] = rule[(size_t)a * KK2 + u * 64 + c1];
                g_rT2[(size_t)u * 4096 + c1 * 64 + a] = rule[(size_t)a * KK2 + c1 * 64 + u];
            }
            __syncthreads();
            if (tid == 0) red_rel(&g_rt, 1);
        }
        spin_lvl(1);
        spin_ctr(&g_rt, 64);

        // U1 / V2 precompute
        {
            float* sRT = smem;
            float* sC1 = smem + 16384;
            for (int u = j; u < 256; u += nbg) {
                const int isV = (u >= 128);
                const int uu = u & 127;
                const int rt = uu >> 4, cc = uu & 15;
                const float* RT = isV ? g_rT2 : g_rT;
                float* OUT = isV ? g_V2 : g_U1;
                for (int idx = tid; idx < 16384; idx += 256) {
                    int xx = idx >> 8, c = idx & 255;
                    sRT[idx] = RT[(size_t)xx * 4096 + cc * 256 + c];
                }
                __syncthreads();
                for (int rblk = 0; rblk < 4; rblk++) {
                    for (int idx = tid; idx < 1024; idx += 256) {
                        int rr = idx >> 6, xx = idx & 63;
                        int row = rt * 64 + rblk * 16 + rr;
                        sC1[idx] = __ldg(&g_chart[cidx(row >> 3, (row >> 3) + 1, row & 7, xx)]);
                    }
                    __syncthreads();
                    for (int rr = 0; rr < 16; rr++) {
                        int row = rt * 64 + rblk * 16 + rr;
                        float acc = 0.f;
                        #pragma unroll 8
                        for (int xx = 0; xx < 64; xx++)
                            acc += sC1[rr * 64 + xx] * sRT[xx * 256 + tid];
                        OUT[(size_t)row * 4096 + cc * 256 + tid] = acc;
                    }
                    __syncthreads();
                }
                if (tid == 0) red_rel(&g_uv, 1);
            }
        }

        // prologue: pair(4) on all bg CTAs (gated on level 2)
        spin_lvl(2);
        pair_level(4, j, nbg, tid);

        // main loop: GEMM(s2) on [0, units) ; pair(s2+1) on [units, nbg)
        for (int s2 = 4; s2 <= Nn; s2++) {
            const int m2 = 65 - s2;
            const int rows2 = m2 * Bb;
            const int ntiles = (m2 + 7) >> 3;
            const int units = ntiles * 32;
            float* const pairn = g_pairs[s2 & 1];

            spin_lvl(s2 - 1);

            if (j < units) {
                const int tile = j >> 5;
                const int chunk = j & 31;
                const int kbase = chunk * 128;
                const int R_t = min(64, rows2 - tile * 64);
                const int lr = tid >> 2, lq = tid & 3;

                spin_ctr(&g_pre_ready[(s2 * 8 + tile) * CSTR], R_t);

                // stage sA = pair (splits 2..s2-2 ONLY; fresh splits live in the front's U1/V2)
                {
                    const int row = tile * 64 + lr;
                    const float4* pb = (const float4*)&rule[(size_t)lr * KK2 + kbase + lq * 4];
                    const float4* pa = (const float4*)&pairn[(size_t)row * KK2 + kbase + lq * 4];
                    #pragma unroll
                    for (int kb = 0; kb < 128; kb += 16) {
                        const int kk = kb + lq * 4;
                        float4 vb = pb[kb >> 2];
                        float4 va = __ldcg(pa + (kb >> 2));
                        sB[(kk + 0) * SSTR + lr] = vb.x;
                        sB[(kk + 1) * SSTR + lr] = vb.y;
                        sB[(kk + 2) * SSTR + lr] = vb.z;
                        sB[(kk + 3) * SSTR + lr] = vb.w;
                        sA[(kk + 0) * SSTR + lr] = va.x;
                        sA[(kk + 1) * SSTR + lr] = va.y;
                        sA[(kk + 2) * SSTR + lr] = va.z;
                        sA[(kk + 3) * SSTR + lr] = va.w;
                    }
                }
                __syncthreads();

                ull acc[4][2];
                #pragma unroll
                for (int i = 0; i < 4; i++) { acc[i][0] = 0ull; acc[i][1] = 0ull; }
                #pragma unroll 8
                for (int k = 0; k < 128; k++) {
                    float4 av = *(const float4*)&sA[k * SSTR + x0];
                    float4 bv = *(const float4*)&sB[k * SSTR + y0r];
                    ull b01 = pack2(bv.x, bv.y), b23 = pack2(bv.z, bv.w);
                    ull a2;
                    a2 = pack2(av.x, av.x); fma2(acc[0][0], a2, b01); fma2(acc[0][1], a2, b23);
                    a2 = pack2(av.y, av.y); fma2(acc[1][0], a2, b01); fma2(acc[1][1], a2, b23);
                    a2 = pack2(av.z, av.z); fma2(acc[2][0], a2, b01); fma2(acc[2][1], a2, b23);
                    a2 = pack2(av.w, av.w); fma2(acc[3][0], a2, b01); fma2(acc[3][1], a2, b23);
                }
                float* part = &g_part[s2 & 1][tile][chunk][0];
                #pragma unroll
                for (int i = 0; i < 4; i++) {
                    float2 e0 = unpk(acc[i][0]), e1 = unpk(acc[i][1]);
                    float4 o; o.x = e0.x; o.y = e0.y; o.z = e1.x; o.w = e1.y;
                    *(float4*)&part[(x0 + i) * 64 + y0r] = o;
                }
                __syncthreads();
                if (tid == 0) red_rel(&g_chunkdone[(s2 * 8 + tile) * CSTR], 1);
            } else if (s2 < Nn) {
                pair_level(s2 + 1, j - units, nbg - units, tid);
            }
        }
    }

    // ===== End barrier + counter reset =====
    gbar(gen + 1, nblk);
    if (bid == 0) {
        for (int i = tid; i < NB1 * 8 * CSTR; i += 256) {
            g_pre_ready[i] = 0;
            g_chunkdone[i] = 0;
        }
        for (int i = tid; i < NB1 * CSTR; i += 256) g_lvlcnt[i] = 0;
        for (int i = tid; i < NF * CSTR; i += 256) g_fdone[i] = 0;
        for (int i = tid; i < 8 * CSTR; i += 256) g_c0[i] = 0;
        if (tid == 0) { g_c0m = 0; g_rt = 0; g_uv = 0; g_lvl = 0; }
    }
}

extern "C" void kernel_launch(void* const* d_in, const int* in_sizes, int n_in,
                              void* d_out, int out_size)
{
    const float* seq   = (const float*)d_in[0];
    const float* rule  = (const float*)d_in[1];
    const float* emit  = (const float*)d_in[2];
    const float* prior = (const float*)d_in[3];
    float* out = (float*)d_out;

    cudaFuncSetAttribute(rbn_persistent, cudaFuncAttributeMaxDynamicSharedMemorySize, SMEM_BYTES);

    int dev = 0, nsm = 1;
    cudaGetDevice(&dev);
    cudaDeviceGetAttribute(&nsm, cudaDevAttrMultiProcessorCount, dev);
    int bpm = 1;
    cudaOccupancyMaxActiveBlocksPerMultiprocessor(&bpm, rbn_persistent, 256, SMEM_BYTES);
    if (bpm < 1) bpm = 1;
    if (bpm > 3) bpm = 3;
    int nblk = nsm * bpm;
    if (nblk > 444) nblk = 444;
    if (nblk < 384) nblk = 384;   // 64 front/publisher + 256 GEMM + >=64 pair CTAs

    rbn_persistent<<<nblk, 256, SMEM_BYTES>>>(seq, rule, emit, prior, out, nblk);
}

// round 15
// speedup vs baseline: 1.3089x; 1.3089x over previous
#include <cuda_runtime.h>

#define Bb 8
#define Nn 64
#define Kk 64
#define Tt 128
#define NB1 65
#define KK2 4096
#define SSTR 68
#define SMEM_BYTES (2 * 128 * SSTR * 4)   // 69632 -> 3 CTAs/SM
#define CSTR 32
#define NF 64

typedef unsigned long long ull;

__device__ __align__(256) float g_chart[NB1 * NB1 * Bb * Kk];
__device__ __align__(256) float g_pairs[2][512 * KK2];
__device__ __align__(256) float g_part[2][8][32][64 * 64];
__device__ __align__(256) float g_U1[512 * 4096];
__device__ __align__(256) float g_V2[512 * 4096];
__device__ __align__(256) float g_rT[64 * 4096];
__device__ __align__(256) float g_rT2[64 * 4096];

__device__ int g_lvl;
__device__ int g_lvlcnt[NB1 * CSTR];
__device__ int g_fdone[NF * CSTR];
__device__ int g_pre_ready[NB1 * 8 * CSTR];
__device__ int g_chunkdone[NB1 * 8 * CSTR];
__device__ int g_c0[8 * CSTR];
__device__ int g_c0m;
__device__ int g_rt;
__device__ int g_uv;
__device__ unsigned g_arrive = 0;
__device__ unsigned g_release = 0;

__device__ __forceinline__ int cidx(int i, int j, int b, int k) {
    return ((i * NB1 + j) * Bb + b) * Kk + k;
}
__device__ __forceinline__ ull pack2(float lo, float hi) {
    ull r; asm("mov.b64 %0, {%1, %2};" : "=l"(r) : "f"(lo), "f"(hi)); return r;
}
__device__ __forceinline__ void fma2(ull& d, ull a, ull b) {
    asm("fma.rn.f32x2 %0, %1, %2, %0;" : "+l"(d) : "l"(a), "l"(b));
}
__device__ __forceinline__ float2 unpk(ull v) {
    float2 o; asm("mov.b64 {%0, %1}, %2;" : "=f"(o.x), "=f"(o.y) : "l"(v)); return o;
}
__device__ __forceinline__ int ld_acq(const int* p) {
    int v; asm volatile("ld.acquire.gpu.global.b32 %0, [%1];" : "=r"(v) : "l"(p) : "memory"); return v;
}
__device__ __forceinline__ void red_rel(int* p, int v) {
    asm volatile("red.release.gpu.global.add.s32 [%0], %1;" :: "l"(p), "r"(v) : "memory");
}
__device__ __forceinline__ int atom_ar(int* p, int v) {
    int o; asm volatile("atom.acq_rel.gpu.global.add.s32 %0, [%1], %2;" : "=r"(o) : "l"(p), "r"(v) : "memory"); return o;
}
__device__ __forceinline__ void st_rel(int* p, int v) {
    asm volatile("st.release.gpu.global.b32 [%0], %1;" :: "l"(p), "r"(v) : "memory");
}
__device__ __forceinline__ void spin_ctr(int* p, int target) {
    if (threadIdx.x == 0) { while (ld_acq(p) < target) { } }
    __syncthreads();
}
__device__ __forceinline__ void spin_lvl(int target) {
    if (threadIdx.x == 0) { while (ld_acq(&g_lvl) < target) { } }
    __syncthreads();
}
__device__ __forceinline__ void gbar(unsigned target, int nblk) {
    __threadfence();
    __syncthreads();
    if (threadIdx.x == 0) {
        unsigned old = atomicAdd(&g_arrive, 1u);
        if (old == (unsigned)(nblk - 1)) {
            g_arrive = 0;
            __threadfence();
            *(volatile unsigned*)&g_release = target;
        } else {
            while ((int)(*(volatile unsigned*)&g_release - target) < 0) __nanosleep(64);
            __threadfence();
        }
    }
    __syncthreads();
}

// pair rank-1 accumulation for level s3 (splits 2..s3-2), rows distributed over [who, np)
// Caller must have gated lvl(s3-2): all inputs are levels <= s3-2.
__device__ __forceinline__ void pair_level(int s3, int who, int np, int tid) {
    const int rows3 = (65 - s3) * Bb;
    float* const pairn = g_pairs[s3 & 1];
    const int tx = tid & 15, ty = tid >> 4;
    const int x0 = ty * 4, y0r = tx * 4;
    for (int u = who; u < rows3; u += np) {
        const int cell = u >> 3, b = u & 7;
        ull acc[4][2];
        #pragma unroll
        for (int i = 0; i < 4; i++) { acc[i][0] = 0ull; acc[i][1] = 0ull; }
        const float* Lbase = &g_chart[cidx(cell, cell, b, x0)];
        const float* Rbase = &g_chart[cidx(cell, cell + s3, b, y0r)];
        #pragma unroll 4
        for (int sp = 2; sp <= s3 - 2; sp++) {
            float4 L = __ldg((const float4*)(Lbase + (size_t)sp * (Bb * Kk)));
            float4 R = __ldg((const float4*)(Rbase + (size_t)sp * (NB1 * Bb * Kk)));
            ull r01 = pack2(R.x, R.y), r23 = pack2(R.z, R.w);
            ull l;
            l = pack2(L.x, L.x); fma2(acc[0][0], l, r01); fma2(acc[0][1], l, r23);
            l = pack2(L.y, L.y); fma2(acc[1][0], l, r01); fma2(acc[1][1], l, r23);
            l = pack2(L.z, L.z); fma2(acc[2][0], l, r01); fma2(acc[2][1], l, r23);
            l = pack2(L.w, L.w); fma2(acc[3][0], l, r01); fma2(acc[3][1], l, r23);
        }
        #pragma unroll
        for (int i = 0; i < 4; i++) {
            float2 e0 = unpk(acc[i][0]), e1 = unpk(acc[i][1]);
            float4 o; o.x = e0.x; o.y = e0.y; o.z = e1.x; o.w = e1.y;
            *(float4*)&pairn[(size_t)u * KK2 + (x0 + i) * Kk + y0r] = o;
        }
        __syncthreads();
        if (tid == 0) red_rel(&g_pre_ready[(s3 * 8 + (u >> 6)) * CSTR], 1);
    }
}

__global__ void __launch_bounds__(256, 3)
rbn_persistent(const float* __restrict__ seq, const float* __restrict__ rule,
               const float* __restrict__ emit, const float* __restrict__ prior,
               float* __restrict__ out, int nblk)
{
    extern __shared__ float smem[];
    const int tid = threadIdx.x;
    const int bid = blockIdx.x;
    const int w = tid >> 5, lane = tid & 31;
    const unsigned gen = *(volatile unsigned*)&g_release;

    // ===== Phase 0: span-1 cells =====
    for (int u = bid; u < Nn * Bb; u += nblk) {
        int i = u >> 3, b = u & 7;
        const float* srow = seq + (b * Nn + i) * Tt;
        #pragma unroll
        for (int aa = 0; aa < 8; aa++) {
            int a = w * 8 + aa;
            float p = 0.f;
            #pragma unroll
            for (int q = 0; q < 4; q++) {
                int t2 = lane + q * 32;
                p += emit[a * Tt + t2] * srow[t2];
            }
            #pragma unroll
            for (int off = 16; off; off >>= 1) p += __shfl_down_sync(0xffffffffu, p, off);
            if (lane == 0) g_chart[cidx(i, i + 1, b, a)] = p;
        }
        __syncthreads();
        if (tid == 0) {
            int old = atom_ar(&g_c0[(u & 7) * CSTR], 1);
            if (old == (Nn * Bb / 8) - 1) {
                int mo = atom_ar(&g_c0m, 1);
                if (mo == 7) st_rel(&g_lvl, 1);
            }
        }
    }

    if (bid < 63) {
        // ===== FRONT CTA f: systolic wavefront + fused partial-reduction =====
        const int f = bid;
        float* sR    = smem;
        float* sPrev = smem + 512;
        float* sAcc  = smem + 1024;
        float* sVp   = smem + 1536;

        spin_ctr(&g_uv, 256);

        const int slot = tid & 127, half = tid >> 7;
        const int b = slot >> 4, quad = slot & 15;
        const float* U1row = &g_U1[((size_t)(f * 8 + b)) << 12];
        const int y0 = half * 32;
        const int tile = f >> 3;

        for (int s = 2; s <= Nn - f; s++) {
            if (s >= 3) spin_ctr(&g_fdone[(f + 1) * CSTR], s - 1);
            if (s >= 4) spin_ctr(&g_chunkdone[(s * 8 + tile) * CSTR], 32);

            if (tid < 128) {
                int bb = tid >> 4, qq = tid & 15;
                *(float4*)&sR[bb * 64 + qq * 4] =
                    __ldg((const float4*)&g_chart[cidx(f + 1, f + s, bb, qq * 4)]);
            } else if (s >= 4) {
                int t2 = tid - 128; int bb = t2 >> 4, qq = t2 & 15;
                const float* pp = &g_part[s & 1][tile][0][((((f & 7) * 8 + bb)) << 6) + qq * 4];
                float4 a4 = make_float4(0.f, 0.f, 0.f, 0.f);
                #pragma unroll
                for (int cc = 0; cc < 32; cc++) {
                    float4 v = __ldcg((const float4*)(pp + (size_t)cc * 4096));
                    a4.x += v.x; a4.y += v.y; a4.z += v.z; a4.w += v.w;
                }
                *(float4*)&sVp[bb * 64 + qq * 4] = a4;
            }
            __syncthreads();

            float4 acc = make_float4(0.f, 0.f, 0.f, 0.f);
            if (s >= 3) {
                const float* V2row = &g_V2[((size_t)((f + s - 1) * 8 + b)) << 12];
                #pragma unroll 8
                for (int y = y0; y < y0 + 32; y++) {
                    float r = sR[b * 64 + y];
                    float4 u = __ldg((const float4*)&U1row[y * 64 + quad * 4]);
                    acc.x += u.x * r; acc.y += u.y * r; acc.z += u.z * r; acc.w += u.w * r;
                    float l = sPrev[b * 64 + y];
                    float4 v = __ldg((const float4*)&V2row[y * 64 + quad * 4]);
                    acc.x += v.x * l; acc.y += v.y * l; acc.z += v.z * l; acc.w += v.w * l;
                }
            } else {
                #pragma unroll 8
                for (int y = y0; y < y0 + 32; y++) {
                    float r = sR[b * 64 + y];
                    float4 u = __ldg((const float4*)&U1row[y * 64 + quad * 4]);
                    acc.x += u.x * r; acc.y += u.y * r; acc.z += u.z * r; acc.w += u.w * r;
                }
            }
            if (half) *(float4*)&sAcc[slot * 4] = acc;
            __syncthreads();
            if (!half) {
                float4 o = acc;
                float4 h = *(const float4*)&sAcc[slot * 4];
                o.x += h.x; o.y += h.y; o.z += h.z; o.w += h.w;
                if (s >= 4) {
                    float4 vp = *(const float4*)&sVp[b * 64 + quad * 4];
                    o.x += vp.x; o.y += vp.y; o.z += vp.z; o.w += vp.w;
                }
                *(float4*)&g_chart[cidx(f, f + s, b, quad * 4)] = o;
                *(float4*)&sPrev[b * 64 + quad * 4] = o;
            }
            __syncthreads();
            if (tid == 0) {
                st_rel(&g_fdone[f * CSTR], s);
                red_rel(&g_lvlcnt[s * CSTR], 1);
            }
        }

        if (f == 0) {
            __syncthreads();
            const int bb = w;
            float p = prior[lane] * sPrev[bb * 64 + lane]
                    + prior[lane + 32] * sPrev[bb * 64 + lane + 32];
            #pragma unroll
            for (int off = 16; off; off >>= 1) p += __shfl_down_sync(0xffffffffu, p, off);
            if (lane == 0) out[bb] = p;
        }
    } else if (bid == 63) {
        // ===== PUBLISHER =====
        for (int s = 2; s <= Nn; s++) {
            spin_ctr(&g_lvlcnt[s * CSTR], 65 - s);
            if (tid == 0) st_rel(&g_lvl, s);
        }
    } else {
        // ===== BACKGROUND =====
        const int j = bid - NF;
        const int nbg = nblk - NF;
        const int tx = tid & 15, ty = tid >> 4;
        const int x0 = ty * 4, y0r = tx * 4;
        float* sA = smem;
        float* sB = smem + 128 * SSTR;

        // rule transposes
        for (int u = j; u < 64; u += nbg) {
            for (int idx = tid; idx < 4096; idx += 256) {
                int c1 = idx >> 6, a = idx & 63;
                g_rT [(size_t)u * 4096 + c1 * 64 + a] = rule[(size_t)a * KK2 + u * 64 + c1];
                g_rT2[(size_t)u * 4096 + c1 * 64 + a] = rule[(size_t)a * KK2 + c1 * 64 + u];
            }
            __syncthreads();
            if (tid == 0) red_rel(&g_rt, 1);
        }
        spin_lvl(1);
        spin_ctr(&g_rt, 64);

        // U1 / V2 precompute
        {
            float* sRT = smem;
            float* sC1 = smem + 16384;
            for (int u = j; u < 256; u += nbg) {
                const int isV = (u >= 128);
                const int uu = u & 127;
                const int rt = uu >> 4, cc = uu & 15;
                const float* RT = isV ? g_rT2 : g_rT;
                float* OUT = isV ? g_V2 : g_U1;
                for (int idx = tid; idx < 16384; idx += 256) {
                    int xx = idx >> 8, c = idx & 255;
                    sRT[idx] = RT[(size_t)xx * 4096 + cc * 256 + c];
                }
                __syncthreads();
                for (int rblk = 0; rblk < 4; rblk++) {
                    for (int idx = tid; idx < 1024; idx += 256) {
                        int rr = idx >> 6, xx = idx & 63;
                        int row = rt * 64 + rblk * 16 + rr;
                        sC1[idx] = __ldg(&g_chart[cidx(row >> 3, (row >> 3) + 1, row & 7, xx)]);
                    }
                    __syncthreads();
                    for (int rr = 0; rr < 16; rr++) {
                        int row = rt * 64 + rblk * 16 + rr;
                        float acc = 0.f;
                        #pragma unroll 8
                        for (int xx = 0; xx < 64; xx++)
                            acc += sC1[rr * 64 + xx] * sRT[xx * 256 + tid];
                        OUT[(size_t)row * 4096 + cc * 256 + tid] = acc;
                    }
                    __syncthreads();
                }
                if (tid == 0) red_rel(&g_uv, 1);
            }
        }

        // prologue: pair(4) on all bg CTAs (gate lvl(2) = lvl(4-2))
        spin_lvl(2);
        pair_level(4, j, nbg, tid);

        // main loop: GEMM(s2) on [0, units) gated ONLY on pre_ready(s2)
        //            (pair(s2) was gated on lvl(s2-2), so GEMM overlaps front(s2-1));
        //            pair(s2+1) on [units, nbg) gated on lvl(s2-1) = lvl((s2+1)-2)
        for (int s2 = 4; s2 <= Nn; s2++) {
            const int m2 = 65 - s2;
            const int rows2 = m2 * Bb;
            const int ntiles = (m2 + 7) >> 3;
            const int units = ntiles * 32;
            float* const pairn = g_pairs[s2 & 1];

            if (j < units) {
                const int tile = j >> 5;
                const int chunk = j & 31;
                const int kbase = chunk * 128;
                const int R_t = min(64, rows2 - tile * 64);
                const int lr = tid >> 2, lq = tid & 3;

                spin_ctr(&g_pre_ready[(s2 * 8 + tile) * CSTR], R_t);

                // stage sA = pair (splits 2..s2-2 ONLY; fresh splits live in the front's U1/V2)
                {
                    const int row = tile * 64 + lr;
                    const float4* pb = (const float4*)&rule[(size_t)lr * KK2 + kbase + lq * 4];
                    const float4* pa = (const float4*)&pairn[(size_t)row * KK2 + kbase + lq * 4];
                    #pragma unroll
                    for (int kb = 0; kb < 128; kb += 16) {
                        const int kk = kb + lq * 4;
                        float4 vb = pb[kb >> 2];
                        float4 va = __ldcg(pa + (kb >> 2));
                        sB[(kk + 0) * SSTR + lr] = vb.x;
                        sB[(kk + 1) * SSTR + lr] = vb.y;
                        sB[(kk + 2) * SSTR + lr] = vb.z;
                        sB[(kk + 3) * SSTR + lr] = vb.w;
                        sA[(kk + 0) * SSTR + lr] = va.x;
                        sA[(kk + 1) * SSTR + lr] = va.y;
                        sA[(kk + 2) * SSTR + lr] = va.z;
                        sA[(kk + 3) * SSTR + lr] = va.w;
                    }
                }
                __syncthreads();

                ull acc[4][2];
                #pragma unroll
                for (int i = 0; i < 4; i++) { acc[i][0] = 0ull; acc[i][1] = 0ull; }
                #pragma unroll 8
                for (int k = 0; k < 128; k++) {
                    float4 av = *(const float4*)&sA[k * SSTR + x0];
                    float4 bv = *(const float4*)&sB[k * SSTR + y0r];
                    ull b01 = pack2(bv.x, bv.y), b23 = pack2(bv.z, bv.w);
                    ull a2;
                    a2 = pack2(av.x, av.x); fma2(acc[0][0], a2, b01); fma2(acc[0][1], a2, b23);
                    a2 = pack2(av.y, av.y); fma2(acc[1][0], a2, b01); fma2(acc[1][1], a2, b23);
                    a2 = pack2(av.z, av.z); fma2(acc[2][0], a2, b01); fma2(acc[2][1], a2, b23);
                    a2 = pack2(av.w, av.w); fma2(acc[3][0], a2, b01); fma2(acc[3][1], a2, b23);
                }
                float* part = &g_part[s2 & 1][tile][chunk][0];
                #pragma unroll
                for (int i = 0; i < 4; i++) {
                    float2 e0 = unpk(acc[i][0]), e1 = unpk(acc[i][1]);
                    float4 o; o.x = e0.x; o.y = e0.y; o.z = e1.x; o.w = e1.y;
                    *(float4*)&part[(x0 + i) * 64 + y0r] = o;
                }
                __syncthreads();
                if (tid == 0) red_rel(&g_chunkdone[(s2 * 8 + tile) * CSTR], 1);
            } else if (s2 < Nn) {
                spin_lvl(s2 - 1);
                pair_level(s2 + 1, j - units, nbg - units, tid);
            }
        }
    }

    // ===== End barrier + counter reset =====
    gbar(gen + 1, nblk);
    if (bid == 0) {
        for (int i = tid; i < NB1 * 8 * CSTR; i += 256) {
            g_pre_ready[i] = 0;
            g_chunkdone[i] = 0;
        }
        for (int i = tid; i < NB1 * CSTR; i += 256) g_lvlcnt[i] = 0;
        for (int i = tid; i < NF * CSTR; i += 256) g_fdone[i] = 0;
        for (int i = tid; i < 8 * CSTR; i += 256) g_c0[i] = 0;
        if (tid == 0) { g_c0m = 0; g_rt = 0; g_uv = 0; g_lvl = 0; }
    }
}

extern "C" void kernel_launch(void* const* d_in, const int* in_sizes, int n_in,
                              void* d_out, int out_size)
{
    const float* seq   = (const float*)d_in[0];
    const float* rule  = (const float*)d_in[1];
    const float* emit  = (const float*)d_in[2];
    const float* prior = (const float*)d_in[3];
    float* out = (float*)d_out;

    cudaFuncSetAttribute(rbn_persistent, cudaFuncAttributeMaxDynamicSharedMemorySize, SMEM_BYTES);

    int dev = 0, nsm = 1;
    cudaGetDevice(&dev);
    cudaDeviceGetAttribute(&nsm, cudaDevAttrMultiProcessorCount, dev);
    int bpm = 1;
    cudaOccupancyMaxActiveBlocksPerMultiprocessor(&bpm, rbn_persistent, 256, SMEM_BYTES);
    if (bpm < 1) bpm = 1;
    if (bpm > 3) bpm = 3;
    int nblk = nsm * bpm;
    if (nblk > 444) nblk = 444;
    if (nblk < 384) nblk = 384;   // 64 front/publisher + 256 GEMM + >=64 pair CTAs

    rbn_persistent<<<nblk, 256, SMEM_BYTES>>>(seq, rule, emit, prior, out, nblk);
}